// round 5
// baseline (speedup 1.0000x reference)
#include <cuda_runtime.h>
#include <cuda_fp16.h>
#include <cstdint>

// Problem dims
#define GB     4
#define GN_SEQ 4096
#define GH     16
#define GD     64
#define GC     1024
#define GM     16384          // GB*GN_SEQ
#define GK     1024
#define GNO    3072           // 3*GC

// GEMM tiling
#define BM 128
#define BN 128
#define BKK 64                          // K elements per stage
#define STAGES 4
#define STAGE_BYTES 49152               // Ahi 16K | Alo 16K | Bhi 16K
#define GEMM_SMEM (STAGES * STAGE_BYTES)  // 192 KB -> 1 CTA/SM, 16 warps

// ---------------- scratch (static device globals; no allocation) -------------
__device__ __half g_Ah[(size_t)GM * GK];     // 32 MB x hi
__device__ __half g_Al[(size_t)GM * GK];     // 32 MB x lo
__device__ __half g_Wh[(size_t)GNO * GK];    //  6 MB w hi
__device__ float g_qkv[(size_t)GM * GNO];    // 192 MB qkv logits
__device__ float g_cpart[64 * 4 * 64 * 64];
__device__ float g_spart[64 * 4 * 64];
__device__ float g_ctx[64 * 64 * 64];

// ---------------- asm helpers ------------------------------------------------
#define LDSM4(r, addr)                                                         \
    asm volatile("ldmatrix.sync.aligned.m8n8.x4.shared.b16 {%0,%1,%2,%3},[%4];"\
                 : "=r"((r)[0]), "=r"((r)[1]), "=r"((r)[2]), "=r"((r)[3])      \
                 : "r"(addr))

#define MMA_F16(d, a, b0, b1)                                                  \
    asm volatile("mma.sync.aligned.m16n8k16.row.col.f32.f16.f16.f32 "          \
                 "{%0,%1,%2,%3},{%4,%5,%6,%7},{%8,%9},{%0,%1,%2,%3};"          \
                 : "+f"((d)[0]), "+f"((d)[1]), "+f"((d)[2]), "+f"((d)[3])      \
                 : "r"((a)[0]), "r"((a)[1]), "r"((a)[2]), "r"((a)[3]),         \
                   "r"(b0), "r"(b1))

#define CP_ASYNC16(dst, src)                                                   \
    asm volatile("cp.async.cg.shared.global [%0],[%1],16;" ::                  \
                 "r"(dst), "l"(src) : "memory")
#define CP_COMMIT() asm volatile("cp.async.commit_group;" ::: "memory")
#define CP_WAIT2()  asm volatile("cp.async.wait_group 2;" ::: "memory")

// ---------------- Kernel 0: fp32 -> fp16 split pre-pass ----------------------
__global__ __launch_bounds__(256) void split_kernel(const float* __restrict__ x,
                                                    const float* __restrict__ w)
{
    const size_t A4 = (size_t)GM * GK / 4;
    const size_t W4 = (size_t)GNO * GK / 4;
    const size_t total = A4 + W4;
    size_t stride = (size_t)gridDim.x * blockDim.x;
    for (size_t i = (size_t)blockIdx.x * blockDim.x + threadIdx.x; i < total; i += stride) {
        if (i < A4) {
            float4 v = ((const float4*)x)[i];
            __half h0 = __float2half_rn(v.x);
            __half h1 = __float2half_rn(v.y);
            __half h2 = __float2half_rn(v.z);
            __half h3 = __float2half_rn(v.w);
            __half l0 = __float2half_rn(v.x - __half2float(h0));
            __half l1 = __float2half_rn(v.y - __half2float(h1));
            __half l2 = __float2half_rn(v.z - __half2float(h2));
            __half l3 = __float2half_rn(v.w - __half2float(h3));
            ((__half2*)g_Ah)[i * 2]     = __halves2half2(h0, h1);
            ((__half2*)g_Ah)[i * 2 + 1] = __halves2half2(h2, h3);
            ((__half2*)g_Al)[i * 2]     = __halves2half2(l0, l1);
            ((__half2*)g_Al)[i * 2 + 1] = __halves2half2(l2, l3);
        } else {
            size_t j = i - A4;
            float4 v = ((const float4*)w)[j];
            ((__half2*)g_Wh)[j * 2]     = __halves2half2(__float2half_rn(v.x),
                                                         __float2half_rn(v.y));
            ((__half2*)g_Wh)[j * 2 + 1] = __halves2half2(__float2half_rn(v.z),
                                                         __float2half_rn(v.w));
        }
    }
}

// ---------------- stage loader ------------------------------------------------
// Stage layout: [Ahi 128x128B | Alo 128x128B | Bhi 128x128B]; within each
// region: row*128B, 16B chunk c stored at (c ^ (row&7))*16  (SW128 pattern).
__device__ __forceinline__ void issue_stage(int kt, int bm, int bn,
                                            unsigned sbase, int t)
{
    const int k0 = kt * BKK;
    const unsigned buf = sbase + (kt & (STAGES - 1)) * STAGE_BYTES;
#pragma unroll
    for (int i = 0; i < 2; ++i) {
        int idx = t + i * 512;          // 0..1023
        int row = idx >> 3;
        int c   = idx & 7;
        unsigned soff = (unsigned)(row * 128 + ((c ^ (row & 7)) << 4));
        const __half* ga = g_Ah + (size_t)(bm + row) * GK + k0 + c * 8;
        CP_ASYNC16(buf + soff, ga);
        const __half* gl = g_Al + (size_t)(bm + row) * GK + k0 + c * 8;
        CP_ASYNC16(buf + 16384 + soff, gl);
        const __half* gb = g_Wh + (size_t)(bn + row) * GK + k0 + c * 8;
        CP_ASYNC16(buf + 32768 + soff, gb);
    }
}

// ---------------- Kernel 1: QKV GEMM (fp16 hi/lo, 16 warps, 4 stages) -------
__global__ __launch_bounds__(512, 1) void qkv_gemm_f16()
{
    extern __shared__ char smraw[];
    const unsigned sbase = (unsigned)__cvta_generic_to_shared(smraw);

    const int t    = threadIdx.x;
    const int bn   = blockIdx.x * BN;     // N fastest: W hot in L2
    const int bm   = blockIdx.y * BM;
    const int lane = t & 31;
    const int warp = t >> 5;
    const int wm   = warp >> 2;           // 0..3 (32-row warp tiles)
    const int wn   = warp & 3;            // 0..3 (32-col warp tiles)

    // per-lane ldmatrix offsets per k16 group g: chunks 2g, 2g+1
    const int lr = lane & 15;
    const int ls = lane >> 4;
    unsigned off[4];
#pragma unroll
    for (int g = 0; g < 4; ++g)
        off[g] = (unsigned)(lr * 128 + (((2 * g) + ls) ^ (lr & 7)) * 16);

    float acc[2][4][4];
#pragma unroll
    for (int i = 0; i < 2; ++i)
#pragma unroll
        for (int j = 0; j < 4; ++j)
#pragma unroll
            for (int c = 0; c < 4; ++c) acc[i][j][c] = 0.0f;

    // prologue: 3 stages in flight
    issue_stage(0, bm, bn, sbase, t); CP_COMMIT();
    issue_stage(1, bm, bn, sbase, t); CP_COMMIT();
    issue_stage(2, bm, bn, sbase, t); CP_COMMIT();

    const int NT = GK / BKK;   // 16
    for (int kt = 0; kt < NT; ++kt) {
        CP_WAIT2();            // stage kt resident (<=2 newer pending)
        __syncthreads();       // all warps done with slot being refilled
        if (kt + 3 < NT)
            issue_stage(kt + 3, bm, bn, sbase, t);
        CP_COMMIT();           // unconditional: group indexing stays exact

        const unsigned slot = sbase + (kt & (STAGES - 1)) * STAGE_BYTES;
        const unsigned aHi  = slot +         (wm * 32) * 128;
        const unsigned aLo  = slot + 16384 + (wm * 32) * 128;
        const unsigned bBs  = slot + 32768 + (wn * 32) * 128;

#pragma unroll
        for (int ks = 0; ks < 4; ++ks) {
            unsigned ah[2][4], al[2][4], bb[2][4];
#pragma unroll
            for (int mt = 0; mt < 2; ++mt) {
                LDSM4(ah[mt], aHi + mt * 2048 + off[ks]);
                LDSM4(al[mt], aLo + mt * 2048 + off[ks]);
            }
#pragma unroll
            for (int p = 0; p < 2; ++p)
                LDSM4(bb[p], bBs + p * 2048 + off[ks]);
#pragma unroll
            for (int mt = 0; mt < 2; ++mt)
#pragma unroll
                for (int p = 0; p < 2; ++p)
#pragma unroll
                    for (int j = 0; j < 2; ++j) {
                        const int nt = p * 2 + j;
                        MMA_F16(acc[mt][nt], ah[mt], bb[p][j], bb[p][j + 2]);
                        MMA_F16(acc[mt][nt], al[mt], bb[p][j], bb[p][j + 2]);
                    }
        }
    }

    // epilogue
    const int g  = lane >> 2;
    const int tc = lane & 3;
#pragma unroll
    for (int mt = 0; mt < 2; ++mt)
#pragma unroll
        for (int nt = 0; nt < 4; ++nt) {
            int row = bm + wm * 32 + mt * 16 + g;
            int col = bn + wn * 32 + nt * 8 + tc * 2;
            *(float2*)(g_qkv + (size_t)row * GNO + col) =
                make_float2(acc[mt][nt][0], acc[mt][nt][1]);
            *(float2*)(g_qkv + (size_t)(row + 8) * GNO + col) =
                make_float2(acc[mt][nt][2], acc[mt][nt][3]);
        }
}

// ---------------- Kernel 2: per-(bh,chunk) partial context + k-exp sums ------
__global__ __launch_bounds__(512) void ctx_partial_kernel()
{
    const int bh    = blockIdx.x;
    const int chunk = blockIdx.y;
    const int b = bh >> 4, h = bh & 15;

    __shared__ __align__(16) float sk[32][64];
    __shared__ __align__(16) float sv[32][64];
    __shared__ __align__(16) float ps[32][64];

    const int t  = threadIdx.x;
    const int li = t >> 4;
    const int lc = t & 15;
    const int dg = t >> 4;
    const int eg = t & 15;

    float acc[2][4] = {{0, 0, 0, 0}, {0, 0, 0, 0}};
    float sacc[4] = {0, 0, 0, 0};

    const float* kbase = g_qkv + ((size_t)b * GN_SEQ) * GNO + 1024 + h * 64;

    for (int tile = 0; tile < 32; ++tile) {
        const int n = chunk * 1024 + tile * 32 + li;
        const float* kr = kbase + (size_t)n * GNO;
        float4 kk = *(const float4*)(kr + lc * 4);
        float4 vv = *(const float4*)(kr + 1024 + lc * 4);
        float4 ek;
        ek.x = __expf(kk.x); ek.y = __expf(kk.y);
        ek.z = __expf(kk.z); ek.w = __expf(kk.w);
        sacc[0] += ek.x; sacc[1] += ek.y; sacc[2] += ek.z; sacc[3] += ek.w;
        ((float4*)sk[li])[lc] = ek;
        ((float4*)sv[li])[lc] = vv;
        __syncthreads();
#pragma unroll 4
        for (int nn = 0; nn < 32; ++nn) {
            float a0 = sk[nn][dg * 2];
            float a1 = sk[nn][dg * 2 + 1];
            float4 v4 = ((float4*)sv[nn])[eg];
            acc[0][0] += a0 * v4.x; acc[0][1] += a0 * v4.y;
            acc[0][2] += a0 * v4.z; acc[0][3] += a0 * v4.w;
            acc[1][0] += a1 * v4.x; acc[1][1] += a1 * v4.y;
            acc[1][2] += a1 * v4.z; acc[1][3] += a1 * v4.w;
        }
        __syncthreads();
    }

    const size_t cbase = ((size_t)(bh * 4 + chunk)) * 4096;
#pragma unroll
    for (int i = 0; i < 2; ++i) {
        int d = dg * 2 + i;
        ((float4*)(g_cpart + cbase + d * 64))[eg] =
            make_float4(acc[i][0], acc[i][1], acc[i][2], acc[i][3]);
    }

    ((float4*)ps[li])[lc] = make_float4(sacc[0], sacc[1], sacc[2], sacc[3]);
    __syncthreads();
    if (t < 64) {
        float s = 0.0f;
#pragma unroll
        for (int i = 0; i < 32; ++i) s += ps[i][t];
        g_spart[(bh * 4 + chunk) * 64 + t] = s;
    }
}

// ---------------- Kernel 3: reduce chunks + normalize context ---------------
__global__ __launch_bounds__(256) void ctx_reduce_kernel()
{
    const int bh = blockIdx.x;
    const int t  = threadIdx.x;
    __shared__ float sinvS[64];
    if (t < 64) {
        const float* sp = g_spart + (size_t)bh * 256 + t;
        float s = sp[0] + sp[64] + sp[128] + sp[192];
        sinvS[t] = 1.0f / s;
    }
    __syncthreads();
    const float* cp = g_cpart + (size_t)bh * 16384;
    for (int idx = t; idx < 4096; idx += 256) {
        float c = cp[idx] + cp[idx + 4096] + cp[idx + 8192] + cp[idx + 12288];
        g_ctx[(size_t)bh * 4096 + idx] = c * sinvS[idx >> 6];
    }
}

// ---------------- Kernel 4: q-softmax (over d) + out = q_soft @ ctx ---------
__global__ __launch_bounds__(256) void out_kernel_f(float* __restrict__ out)
{
    const int nb = blockIdx.x;
    const int bh = blockIdx.y;
    const int b = bh >> 4, h = bh & 15;

    __shared__ __align__(16) float sctx[64][64];
    __shared__ __align__(16) float sq[64][68];
    __shared__ float prow[64][4];
    __shared__ float sinv[64];

    const int t = threadIdx.x;

    const float4* cg = (const float4*)(g_ctx + (size_t)bh * 4096);
    float4* cs = (float4*)sctx;
#pragma unroll
    for (int j = 0; j < 4; ++j) cs[t + 256 * j] = cg[t + 256 * j];

    const int r  = t >> 2;
    const int qp = t & 3;
    const float* qrow = g_qkv + ((size_t)(b * GN_SEQ + nb * 64 + r)) * GNO + h * 64;
    float psum = 0.0f;
#pragma unroll
    for (int c4 = 0; c4 < 4; ++c4) {
        int d0 = qp * 16 + c4 * 4;
        float4 qv = *(const float4*)(qrow + d0);
        float e0 = __expf(qv.x), e1 = __expf(qv.y), e2 = __expf(qv.z), e3 = __expf(qv.w);
        sq[r][d0] = e0; sq[r][d0 + 1] = e1; sq[r][d0 + 2] = e2; sq[r][d0 + 3] = e3;
        psum += e0 + e1 + e2 + e3;
    }
    prow[r][qp] = psum;
    __syncthreads();
    if (t < 64)
        sinv[t] = 0.125f / (prow[t][0] + prow[t][1] + prow[t][2] + prow[t][3]);
    __syncthreads();

    {
        float myinv = sinv[r];
#pragma unroll
        for (int c4 = 0; c4 < 4; ++c4) {
            int d0 = qp * 16 + c4 * 4;
            sq[r][d0] *= myinv; sq[r][d0 + 1] *= myinv;
            sq[r][d0 + 2] *= myinv; sq[r][d0 + 3] *= myinv;
        }
    }
    __syncthreads();

    const int rg  = t >> 4;
    const int egx = t & 15;
    float acc[4][4] = {{0}};
#pragma unroll 4
    for (int d = 0; d < 64; ++d) {
        float4 c4v = ((float4*)sctx[d])[egx];
#pragma unroll
        for (int i = 0; i < 4; ++i) {
            float qv = sq[rg * 4 + i][d];
            acc[i][0] += qv * c4v.x; acc[i][1] += qv * c4v.y;
            acc[i][2] += qv * c4v.z; acc[i][3] += qv * c4v.w;
        }
    }
#pragma unroll
    for (int i = 0; i < 4; ++i) {
        int n = nb * 64 + rg * 4 + i;
        ((float4*)(out + ((size_t)bh * GN_SEQ + n) * 64))[egx] =
            make_float4(acc[i][0], acc[i][1], acc[i][2], acc[i][3]);
    }
}

// ---------------- launcher ----------------------------------------------------
extern "C" void kernel_launch(void* const* d_in, const int* in_sizes, int n_in,
                              void* d_out, int out_size)
{
    const float* x = (const float*)d_in[0];     // [4,4096,1024]
    const float* w = (const float*)d_in[1];     // [3072,1024]
    float* out = (float*)d_out;                 // [4,16,4096,64]

    cudaFuncSetAttribute(qkv_gemm_f16,
                         cudaFuncAttributeMaxDynamicSharedMemorySize, GEMM_SMEM);

    split_kernel<<<4096, 256>>>(x, w);

    dim3 gGemm(GNO / BN, GM / BM);              // (24, 128) — N fastest for L2 reuse
    qkv_gemm_f16<<<gGemm, 512, GEMM_SMEM>>>();

    dim3 gCtx(64, 4);
    ctx_partial_kernel<<<gCtx, 512>>>();

    ctx_reduce_kernel<<<64, 256>>>();

    dim3 gOut(64, 64);
    out_kernel_f<<<gOut, 256>>>(out);
}

// round 6
// speedup vs baseline: 1.0217x; 1.0217x over previous
#include <cuda_runtime.h>
#include <cuda_fp16.h>
#include <cstdint>

// Problem dims
#define GB     4
#define GN_SEQ 4096
#define GH     16
#define GD     64
#define GC     1024
#define GM     16384          // GB*GN_SEQ
#define GK     1024
#define GNO    3072           // 3*GC

// GEMM tiling: CTA 128x256, 8 warps of 64x64, BKK=64, 3 stages
#define BM 128
#define BN 256
#define BKK 64
#define STAGES 3
#define STAGE_BYTES 65536               // Ahi 16K | Alo 16K | B 32K
#define GEMM_SMEM (STAGES * STAGE_BYTES)  // 192 KB

// ---------------- scratch (static device globals; no allocation) -------------
__device__ __half g_Ah[(size_t)GM * GK];     // 32 MB x hi
__device__ __half g_Al[(size_t)GM * GK];     // 32 MB x lo
__device__ __half g_Wh[(size_t)GNO * GK];    //  6 MB w hi
__device__ float g_qkv[(size_t)GM * GNO];    // 192 MB qkv logits
__device__ float g_cpart[64 * 4 * 64 * 64];
__device__ float g_spart[64 * 4 * 64];
__device__ float g_ctx[64 * 64 * 64];

// ---------------- asm helpers ------------------------------------------------
#define LDSM4(r, addr)                                                         \
    asm volatile("ldmatrix.sync.aligned.m8n8.x4.shared.b16 {%0,%1,%2,%3},[%4];"\
                 : "=r"((r)[0]), "=r"((r)[1]), "=r"((r)[2]), "=r"((r)[3])      \
                 : "r"(addr))

#define MMA_F16(d, a, b0, b1)                                                  \
    asm volatile("mma.sync.aligned.m16n8k16.row.col.f32.f16.f16.f32 "          \
                 "{%0,%1,%2,%3},{%4,%5,%6,%7},{%8,%9},{%0,%1,%2,%3};"          \
                 : "+f"((d)[0]), "+f"((d)[1]), "+f"((d)[2]), "+f"((d)[3])      \
                 : "r"((a)[0]), "r"((a)[1]), "r"((a)[2]), "r"((a)[3]),         \
                   "r"(b0), "r"(b1))

#define CP_ASYNC16(dst, src)                                                   \
    asm volatile("cp.async.cg.shared.global [%0],[%1],16;" ::                  \
                 "r"(dst), "l"(src) : "memory")
#define CP_COMMIT() asm volatile("cp.async.commit_group;" ::: "memory")
#define CP_WAIT1()  asm volatile("cp.async.wait_group 1;" ::: "memory")

// ---------------- Kernel 0: fp32 -> fp16 split pre-pass ----------------------
__global__ __launch_bounds__(256) void split_kernel(const float* __restrict__ x,
                                                    const float* __restrict__ w)
{
    const size_t A4 = (size_t)GM * GK / 4;
    const size_t W4 = (size_t)GNO * GK / 4;
    const size_t total = A4 + W4;
    size_t stride = (size_t)gridDim.x * blockDim.x;
    for (size_t i = (size_t)blockIdx.x * blockDim.x + threadIdx.x; i < total; i += stride) {
        if (i < A4) {
            float4 v = ((const float4*)x)[i];
            __half h0 = __float2half_rn(v.x);
            __half h1 = __float2half_rn(v.y);
            __half h2 = __float2half_rn(v.z);
            __half h3 = __float2half_rn(v.w);
            __half l0 = __float2half_rn(v.x - __half2float(h0));
            __half l1 = __float2half_rn(v.y - __half2float(h1));
            __half l2 = __float2half_rn(v.z - __half2float(h2));
            __half l3 = __float2half_rn(v.w - __half2float(h3));
            ((__half2*)g_Ah)[i * 2]     = __halves2half2(h0, h1);
            ((__half2*)g_Ah)[i * 2 + 1] = __halves2half2(h2, h3);
            ((__half2*)g_Al)[i * 2]     = __halves2half2(l0, l1);
            ((__half2*)g_Al)[i * 2 + 1] = __halves2half2(l2, l3);
        } else {
            size_t j = i - A4;
            float4 v = ((const float4*)w)[j];
            ((__half2*)g_Wh)[j * 2]     = __halves2half2(__float2half_rn(v.x),
                                                         __float2half_rn(v.y));
            ((__half2*)g_Wh)[j * 2 + 1] = __halves2half2(__float2half_rn(v.z),
                                                         __float2half_rn(v.w));
        }
    }
}

// ---------------- stage loader ------------------------------------------------
// Stage layout: [Ahi 128 rows | Alo 128 rows | B 256 rows], each row 128B;
// 16B chunk c stored at (c ^ (row&7))*16 within the row (SW128 pattern).
__device__ __forceinline__ void issue_stage(int kt, int bm, int bn,
                                            unsigned sbase, int t)
{
    const int k0 = kt * BKK;
    const unsigned buf = sbase + (kt % STAGES) * STAGE_BYTES;
    // A hi + lo: 1024 chunks each
#pragma unroll
    for (int j = 0; j < 4; ++j) {
        int idx = t + j * 256;          // 0..1023
        int row = idx >> 3;
        int c   = idx & 7;
        unsigned soff = (unsigned)(row * 128 + ((c ^ (row & 7)) << 4));
        const __half* ga = g_Ah + (size_t)(bm + row) * GK + k0 + c * 8;
        CP_ASYNC16(buf + soff, ga);
        const __half* gl = g_Al + (size_t)(bm + row) * GK + k0 + c * 8;
        CP_ASYNC16(buf + 16384 + soff, gl);
    }
    // B: 2048 chunks (256 rows x 8)
#pragma unroll
    for (int j = 0; j < 8; ++j) {
        int idx = t + j * 256;          // 0..2047
        int row = idx >> 3;
        int c   = idx & 7;
        unsigned soff = (unsigned)(row * 128 + ((c ^ (row & 7)) << 4));
        const __half* gb = g_Wh + (size_t)(bn + row) * GK + k0 + c * 8;
        CP_ASYNC16(buf + 32768 + soff, gb);
    }
}

// ---------------- Kernel 1: QKV GEMM (fp16 hi/lo, 8 warps of 64x64) ---------
__global__ __launch_bounds__(256, 1) void qkv_gemm_f16()
{
    extern __shared__ char smraw[];
    const unsigned sbase = (unsigned)__cvta_generic_to_shared(smraw);

    const int t    = threadIdx.x;
    const int bn   = blockIdx.x * BN;     // N fastest: W hot in L2
    const int bm   = blockIdx.y * BM;
    const int lane = t & 31;
    const int warp = t >> 5;
    const int wm   = warp >> 2;           // 0..1 (64-row warp tiles)
    const int wn   = warp & 3;            // 0..3 (64-col warp tiles)

    // per-lane ldmatrix offsets per k16 group g: chunks 2g, 2g+1
    const int lr = lane & 15;
    const int ls = lane >> 4;
    unsigned off[4];
#pragma unroll
    for (int g = 0; g < 4; ++g)
        off[g] = (unsigned)(lr * 128 + (((2 * g) + ls) ^ (lr & 7)) * 16);

    float acc[4][8][4];
#pragma unroll
    for (int i = 0; i < 4; ++i)
#pragma unroll
        for (int j = 0; j < 8; ++j)
#pragma unroll
            for (int c = 0; c < 4; ++c) acc[i][j][c] = 0.0f;

    // prologue: 2 stages in flight
    issue_stage(0, bm, bn, sbase, t); CP_COMMIT();
    issue_stage(1, bm, bn, sbase, t); CP_COMMIT();

    const int NT = GK / BKK;   // 16
    for (int kt = 0; kt < NT; ++kt) {
        CP_WAIT1();            // stage kt resident (<=1 newer pending)
        __syncthreads();       // all warps done with slot being refilled
        if (kt + 2 < NT)
            issue_stage(kt + 2, bm, bn, sbase, t);   // overlaps compute kt
        CP_COMMIT();           // unconditional: group indexing stays exact

        const unsigned slot = sbase + (kt % STAGES) * STAGE_BYTES;
        const unsigned aHi  = slot +         (wm * 64) * 128;
        const unsigned aLo  = slot + 16384 + (wm * 64) * 128;
        const unsigned bBs  = slot + 32768 + (wn * 64) * 128;

#pragma unroll
        for (int ks = 0; ks < 4; ++ks) {
            unsigned ah[4][4], al[4][4], bb[4][4];
#pragma unroll
            for (int mt = 0; mt < 4; ++mt) {
                LDSM4(ah[mt], aHi + mt * 2048 + off[ks]);
                LDSM4(al[mt], aLo + mt * 2048 + off[ks]);
            }
#pragma unroll
            for (int p = 0; p < 4; ++p)
                LDSM4(bb[p], bBs + p * 2048 + off[ks]);
#pragma unroll
            for (int mt = 0; mt < 4; ++mt)
#pragma unroll
                for (int p = 0; p < 4; ++p)
#pragma unroll
                    for (int j = 0; j < 2; ++j) {
                        const int nt = p * 2 + j;
                        MMA_F16(acc[mt][nt], ah[mt], bb[p][j], bb[p][j + 2]);
                        MMA_F16(acc[mt][nt], al[mt], bb[p][j], bb[p][j + 2]);
                    }
        }
    }

    // epilogue
    const int g  = lane >> 2;
    const int tc = lane & 3;
#pragma unroll
    for (int mt = 0; mt < 4; ++mt)
#pragma unroll
        for (int nt = 0; nt < 8; ++nt) {
            int row = bm + wm * 64 + mt * 16 + g;
            int col = bn + wn * 64 + nt * 8 + tc * 2;
            *(float2*)(g_qkv + (size_t)row * GNO + col) =
                make_float2(acc[mt][nt][0], acc[mt][nt][1]);
            *(float2*)(g_qkv + (size_t)(row + 8) * GNO + col) =
                make_float2(acc[mt][nt][2], acc[mt][nt][3]);
        }
}

// ---------------- Kernel 2: per-(bh,chunk) partial context + k-exp sums ------
__global__ __launch_bounds__(512) void ctx_partial_kernel()
{
    const int bh    = blockIdx.x;
    const int chunk = blockIdx.y;
    const int b = bh >> 4, h = bh & 15;

    __shared__ __align__(16) float sk[32][64];
    __shared__ __align__(16) float sv[32][64];
    __shared__ __align__(16) float ps[32][64];

    const int t  = threadIdx.x;
    const int li = t >> 4;
    const int lc = t & 15;
    const int dg = t >> 4;
    const int eg = t & 15;

    float acc[2][4] = {{0, 0, 0, 0}, {0, 0, 0, 0}};
    float sacc[4] = {0, 0, 0, 0};

    const float* kbase = g_qkv + ((size_t)b * GN_SEQ) * GNO + 1024 + h * 64;

    for (int tile = 0; tile < 32; ++tile) {
        const int n = chunk * 1024 + tile * 32 + li;
        const float* kr = kbase + (size_t)n * GNO;
        float4 kk = *(const float4*)(kr + lc * 4);
        float4 vv = *(const float4*)(kr + 1024 + lc * 4);
        float4 ek;
        ek.x = __expf(kk.x); ek.y = __expf(kk.y);
        ek.z = __expf(kk.z); ek.w = __expf(kk.w);
        sacc[0] += ek.x; sacc[1] += ek.y; sacc[2] += ek.z; sacc[3] += ek.w;
        ((float4*)sk[li])[lc] = ek;
        ((float4*)sv[li])[lc] = vv;
        __syncthreads();
#pragma unroll 4
        for (int nn = 0; nn < 32; ++nn) {
            float a0 = sk[nn][dg * 2];
            float a1 = sk[nn][dg * 2 + 1];
            float4 v4 = ((float4*)sv[nn])[eg];
            acc[0][0] += a0 * v4.x; acc[0][1] += a0 * v4.y;
            acc[0][2] += a0 * v4.z; acc[0][3] += a0 * v4.w;
            acc[1][0] += a1 * v4.x; acc[1][1] += a1 * v4.y;
            acc[1][2] += a1 * v4.z; acc[1][3] += a1 * v4.w;
        }
        __syncthreads();
    }

    const size_t cbase = ((size_t)(bh * 4 + chunk)) * 4096;
#pragma unroll
    for (int i = 0; i < 2; ++i) {
        int d = dg * 2 + i;
        ((float4*)(g_cpart + cbase + d * 64))[eg] =
            make_float4(acc[i][0], acc[i][1], acc[i][2], acc[i][3]);
    }

    ((float4*)ps[li])[lc] = make_float4(sacc[0], sacc[1], sacc[2], sacc[3]);
    __syncthreads();
    if (t < 64) {
        float s = 0.0f;
#pragma unroll
        for (int i = 0; i < 32; ++i) s += ps[i][t];
        g_spart[(bh * 4 + chunk) * 64 + t] = s;
    }
}

// ---------------- Kernel 3: reduce chunks + normalize context ---------------
__global__ __launch_bounds__(256) void ctx_reduce_kernel()
{
    const int bh = blockIdx.x;
    const int q  = blockIdx.y;       // quarter of the 4096 elements
    const int t  = threadIdx.x;
    __shared__ float sinvS[64];
    if (t < 64) {
        const float* sp = g_spart + (size_t)bh * 256 + t;
        float s = sp[0] + sp[64] + sp[128] + sp[192];
        sinvS[t] = 1.0f / s;
    }
    __syncthreads();
    const float* cp = g_cpart + (size_t)bh * 16384;
    for (int idx = q * 1024 + t; idx < q * 1024 + 1024; idx += 256) {
        float c = cp[idx] + cp[idx + 4096] + cp[idx + 8192] + cp[idx + 12288];
        g_ctx[(size_t)bh * 4096 + idx] = c * sinvS[idx >> 6];
    }
}

// ---------------- Kernel 4: q-softmax (over d) + out = q_soft @ ctx ---------
__global__ __launch_bounds__(256) void out_kernel_f(float* __restrict__ out)
{
    const int nb = blockIdx.x;
    const int bh = blockIdx.y;
    const int b = bh >> 4, h = bh & 15;

    __shared__ __align__(16) float sctx[64][64];
    __shared__ __align__(16) float sq[64][68];
    __shared__ float prow[64][4];
    __shared__ float sinv[64];

    const int t = threadIdx.x;

    const float4* cg = (const float4*)(g_ctx + (size_t)bh * 4096);
    float4* cs = (float4*)sctx;
#pragma unroll
    for (int j = 0; j < 4; ++j) cs[t + 256 * j] = cg[t + 256 * j];

    const int r  = t >> 2;
    const int qp = t & 3;
    const float* qrow = g_qkv + ((size_t)(b * GN_SEQ + nb * 64 + r)) * GNO + h * 64;
    float psum = 0.0f;
#pragma unroll
    for (int c4 = 0; c4 < 4; ++c4) {
        int d0 = qp * 16 + c4 * 4;
        float4 qv = *(const float4*)(qrow + d0);
        float e0 = __expf(qv.x), e1 = __expf(qv.y), e2 = __expf(qv.z), e3 = __expf(qv.w);
        sq[r][d0] = e0; sq[r][d0 + 1] = e1; sq[r][d0 + 2] = e2; sq[r][d0 + 3] = e3;
        psum += e0 + e1 + e2 + e3;
    }
    prow[r][qp] = psum;
    __syncthreads();
    if (t < 64)
        sinv[t] = 0.125f / (prow[t][0] + prow[t][1] + prow[t][2] + prow[t][3]);
    __syncthreads();

    {
        float myinv = sinv[r];
#pragma unroll
        for (int c4 = 0; c4 < 4; ++c4) {
            int d0 = qp * 16 + c4 * 4;
            sq[r][d0] *= myinv; sq[r][d0 + 1] *= myinv;
            sq[r][d0 + 2] *= myinv; sq[r][d0 + 3] *= myinv;
        }
    }
    __syncthreads();

    const int rg  = t >> 4;
    const int egx = t & 15;
    float acc[4][4] = {{0}};
#pragma unroll 4
    for (int d = 0; d < 64; ++d) {
        float4 c4v = ((float4*)sctx[d])[egx];
#pragma unroll
        for (int i = 0; i < 4; ++i) {
            float qv = sq[rg * 4 + i][d];
            acc[i][0] += qv * c4v.x; acc[i][1] += qv * c4v.y;
            acc[i][2] += qv * c4v.z; acc[i][3] += qv * c4v.w;
        }
    }
#pragma unroll
    for (int i = 0; i < 4; ++i) {
        int n = nb * 64 + rg * 4 + i;
        ((float4*)(out + ((size_t)bh * GN_SEQ + n) * 64))[egx] =
            make_float4(acc[i][0], acc[i][1], acc[i][2], acc[i][3]);
    }
}

// ---------------- launcher ----------------------------------------------------
extern "C" void kernel_launch(void* const* d_in, const int* in_sizes, int n_in,
                              void* d_out, int out_size)
{
    const float* x = (const float*)d_in[0];     // [4,4096,1024]
    const float* w = (const float*)d_in[1];     // [3072,1024]
    float* out = (float*)d_out;                 // [4,16,4096,64]

    cudaFuncSetAttribute(qkv_gemm_f16,
                         cudaFuncAttributeMaxDynamicSharedMemorySize, GEMM_SMEM);

    split_kernel<<<4096, 256>>>(x, w);

    dim3 gGemm(GNO / BN, GM / BM);              // (12, 128) — N fastest for L2 reuse
    qkv_gemm_f16<<<gGemm, 256, GEMM_SMEM>>>();

    dim3 gCtx(64, 4);
    ctx_partial_kernel<<<gCtx, 512>>>();

    dim3 gRed(64, 4);
    ctx_reduce_kernel<<<gRed, 256>>>();

    dim3 gOut(64, 64);
    out_kernel_f<<<gOut, 256>>>(out);
}

// round 7
// speedup vs baseline: 1.6036x; 1.5696x over previous
#include <cuda_runtime.h>
#include <cuda_fp16.h>
#include <cstdint>

// Problem dims
#define GB     4
#define GN_SEQ 4096
#define GH     16
#define GD     64
#define GC     1024
#define GM     16384          // GB*GN_SEQ
#define GK     1024
#define GNO    3072           // 3*GC

// GEMM tiling: CTA 128x128, 8 warps of 64x32, BKK=64, 3 stages, occ 2
#define BM 128
#define BN 128
#define BKK 64
#define STAGES 3
#define STAGE_BYTES 32768               // A 16K | B 16K
#define GEMM_SMEM (STAGES * STAGE_BYTES)  // 96 KB -> 2 CTAs/SM

// ---------------- scratch (static device globals; no allocation) -------------
__device__ __half g_Ah[(size_t)GM * GK];     // 32 MB x fp16
__device__ __half g_Wh[(size_t)GNO * GK];    //  6 MB w fp16
__device__ float g_qkv[(size_t)GM * GNO];    // 192 MB qkv logits
__device__ float g_cpart[64 * 4 * 64 * 64];
__device__ float g_spart[64 * 4 * 64];
__device__ float g_ctx[64 * 64 * 64];

// ---------------- asm helpers ------------------------------------------------
#define LDSM4(r, addr)                                                         \
    asm volatile("ldmatrix.sync.aligned.m8n8.x4.shared.b16 {%0,%1,%2,%3},[%4];"\
                 : "=r"((r)[0]), "=r"((r)[1]), "=r"((r)[2]), "=r"((r)[3])      \
                 : "r"(addr))

#define MMA_F16(d, a, b0, b1)                                                  \
    asm volatile("mma.sync.aligned.m16n8k16.row.col.f32.f16.f16.f32 "          \
                 "{%0,%1,%2,%3},{%4,%5,%6,%7},{%8,%9},{%0,%1,%2,%3};"          \
                 : "+f"((d)[0]), "+f"((d)[1]), "+f"((d)[2]), "+f"((d)[3])      \
                 : "r"((a)[0]), "r"((a)[1]), "r"((a)[2]), "r"((a)[3]),         \
                   "r"(b0), "r"(b1))

#define CP_ASYNC16(dst, src)                                                   \
    asm volatile("cp.async.cg.shared.global [%0],[%1],16;" ::                  \
                 "r"(dst), "l"(src) : "memory")
#define CP_COMMIT() asm volatile("cp.async.commit_group;" ::: "memory")
#define CP_WAIT1()  asm volatile("cp.async.wait_group 1;" ::: "memory")

// ---------------- Kernel 0: fp32 -> fp16 convert pre-pass --------------------
__global__ __launch_bounds__(256) void split_kernel(const float* __restrict__ x,
                                                    const float* __restrict__ w)
{
    const size_t A4 = (size_t)GM * GK / 4;
    const size_t W4 = (size_t)GNO * GK / 4;
    const size_t total = A4 + W4;
    size_t stride = (size_t)gridDim.x * blockDim.x;
    for (size_t i = (size_t)blockIdx.x * blockDim.x + threadIdx.x; i < total; i += stride) {
        if (i < A4) {
            float4 v = ((const float4*)x)[i];
            ((__half2*)g_Ah)[i * 2]     = __halves2half2(__float2half_rn(v.x),
                                                         __float2half_rn(v.y));
            ((__half2*)g_Ah)[i * 2 + 1] = __halves2half2(__float2half_rn(v.z),
                                                         __float2half_rn(v.w));
        } else {
            size_t j = i - A4;
            float4 v = ((const float4*)w)[j];
            ((__half2*)g_Wh)[j * 2]     = __halves2half2(__float2half_rn(v.x),
                                                         __float2half_rn(v.y));
            ((__half2*)g_Wh)[j * 2 + 1] = __halves2half2(__float2half_rn(v.z),
                                                         __float2half_rn(v.w));
        }
    }
}

// ---------------- stage loader ------------------------------------------------
// Stage layout: [A 128 rows | B 128 rows], each row 128B;
// 16B chunk c stored at (c ^ (row&7))*16 within the row (SW128 pattern).
__device__ __forceinline__ void issue_stage(int kt, int bm, int bn,
                                            unsigned sbase, int t)
{
    const int k0 = kt * BKK;
    const unsigned buf = sbase + (kt % STAGES) * STAGE_BYTES;
#pragma unroll
    for (int j = 0; j < 4; ++j) {
        int idx = t + j * 256;          // 0..1023
        int row = idx >> 3;
        int c   = idx & 7;
        unsigned soff = (unsigned)(row * 128 + ((c ^ (row & 7)) << 4));
        const __half* ga = g_Ah + (size_t)(bm + row) * GK + k0 + c * 8;
        CP_ASYNC16(buf + soff, ga);
        const __half* gb = g_Wh + (size_t)(bn + row) * GK + k0 + c * 8;
        CP_ASYNC16(buf + 16384 + soff, gb);
    }
}

// ---------------- Kernel 1: QKV GEMM (single fp16 MMA, occ 2) ---------------
__global__ __launch_bounds__(256, 2) void qkv_gemm_f16()
{
    extern __shared__ char smraw[];
    const unsigned sbase = (unsigned)__cvta_generic_to_shared(smraw);

    const int t    = threadIdx.x;
    const int bn   = blockIdx.x * BN;     // N fastest: W hot in L2
    const int bm   = blockIdx.y * BM;
    const int lane = t & 31;
    const int warp = t >> 5;
    const int wm   = warp >> 2;           // 0..1 (64-row warp tiles)
    const int wn   = warp & 3;            // 0..3 (32-col warp tiles)

    // per-lane ldmatrix offsets per k16 group g: chunks 2g, 2g+1
    const int lr = lane & 15;
    const int ls = lane >> 4;
    unsigned off[4];
#pragma unroll
    for (int g = 0; g < 4; ++g)
        off[g] = (unsigned)(lr * 128 + (((2 * g) + ls) ^ (lr & 7)) * 16);

    float acc[4][4][4];
#pragma unroll
    for (int i = 0; i < 4; ++i)
#pragma unroll
        for (int j = 0; j < 4; ++j)
#pragma unroll
            for (int c = 0; c < 4; ++c) acc[i][j][c] = 0.0f;

    // prologue: 2 stages in flight
    issue_stage(0, bm, bn, sbase, t); CP_COMMIT();
    issue_stage(1, bm, bn, sbase, t); CP_COMMIT();

    const int NT = GK / BKK;   // 16
    for (int kt = 0; kt < NT; ++kt) {
        CP_WAIT1();            // stage kt resident (<=1 newer pending)
        __syncthreads();       // all warps done with slot being refilled
        if (kt + 2 < NT)
            issue_stage(kt + 2, bm, bn, sbase, t);   // overlaps compute kt
        CP_COMMIT();           // unconditional: group indexing stays exact

        const unsigned slot = sbase + (kt % STAGES) * STAGE_BYTES;
        const unsigned aBs  = slot +         (wm * 64) * 128;
        const unsigned bBs  = slot + 16384 + (wn * 32) * 128;

#pragma unroll
        for (int ks = 0; ks < 4; ++ks) {
            unsigned ah[4][4], bb[2][4];
#pragma unroll
            for (int mt = 0; mt < 4; ++mt)
                LDSM4(ah[mt], aBs + mt * 2048 + off[ks]);
#pragma unroll
            for (int p = 0; p < 2; ++p)
                LDSM4(bb[p], bBs + p * 2048 + off[ks]);
#pragma unroll
            for (int mt = 0; mt < 4; ++mt)
#pragma unroll
                for (int p = 0; p < 2; ++p)
#pragma unroll
                    for (int j = 0; j < 2; ++j)
                        MMA_F16(acc[mt][p * 2 + j], ah[mt], bb[p][j], bb[p][j + 2]);
        }
    }

    // epilogue
    const int g  = lane >> 2;
    const int tc = lane & 3;
#pragma unroll
    for (int mt = 0; mt < 4; ++mt)
#pragma unroll
        for (int nt = 0; nt < 4; ++nt) {
            int row = bm + wm * 64 + mt * 16 + g;
            int col = bn + wn * 32 + nt * 8 + tc * 2;
            *(float2*)(g_qkv + (size_t)row * GNO + col) =
                make_float2(acc[mt][nt][0], acc[mt][nt][1]);
            *(float2*)(g_qkv + (size_t)(row + 8) * GNO + col) =
                make_float2(acc[mt][nt][2], acc[mt][nt][3]);
        }
}

// ---------------- Kernel 2: per-(bh,chunk) partial context + k-exp sums ------
__global__ __launch_bounds__(512) void ctx_partial_kernel()
{
    const int bh    = blockIdx.x;
    const int chunk = blockIdx.y;
    const int b = bh >> 4, h = bh & 15;

    __shared__ __align__(16) float sk[32][64];
    __shared__ __align__(16) float sv[32][64];
    __shared__ __align__(16) float ps[32][64];

    const int t  = threadIdx.x;
    const int li = t >> 4;
    const int lc = t & 15;
    const int dg = t >> 4;
    const int eg = t & 15;

    float acc[2][4] = {{0, 0, 0, 0}, {0, 0, 0, 0}};
    float sacc[4] = {0, 0, 0, 0};

    const float* kbase = g_qkv + ((size_t)b * GN_SEQ) * GNO + 1024 + h * 64;

    for (int tile = 0; tile < 32; ++tile) {
        const int n = chunk * 1024 + tile * 32 + li;
        const float* kr = kbase + (size_t)n * GNO;
        float4 kk = *(const float4*)(kr + lc * 4);
        float4 vv = *(const float4*)(kr + 1024 + lc * 4);
        float4 ek;
        ek.x = __expf(kk.x); ek.y = __expf(kk.y);
        ek.z = __expf(kk.z); ek.w = __expf(kk.w);
        sacc[0] += ek.x; sacc[1] += ek.y; sacc[2] += ek.z; sacc[3] += ek.w;
        ((float4*)sk[li])[lc] = ek;
        ((float4*)sv[li])[lc] = vv;
        __syncthreads();
#pragma unroll 4
        for (int nn = 0; nn < 32; ++nn) {
            float a0 = sk[nn][dg * 2];
            float a1 = sk[nn][dg * 2 + 1];
            float4 v4 = ((float4*)sv[nn])[eg];
            acc[0][0] += a0 * v4.x; acc[0][1] += a0 * v4.y;
            acc[0][2] += a0 * v4.z; acc[0][3] += a0 * v4.w;
            acc[1][0] += a1 * v4.x; acc[1][1] += a1 * v4.y;
            acc[1][2] += a1 * v4.z; acc[1][3] += a1 * v4.w;
        }
        __syncthreads();
    }

    const size_t cbase = ((size_t)(bh * 4 + chunk)) * 4096;
#pragma unroll
    for (int i = 0; i < 2; ++i) {
        int d = dg * 2 + i;
        ((float4*)(g_cpart + cbase + d * 64))[eg] =
            make_float4(acc[i][0], acc[i][1], acc[i][2], acc[i][3]);
    }

    ((float4*)ps[li])[lc] = make_float4(sacc[0], sacc[1], sacc[2], sacc[3]);
    __syncthreads();
    if (t < 64) {
        float s = 0.0f;
#pragma unroll
        for (int i = 0; i < 32; ++i) s += ps[i][t];
        g_spart[(bh * 4 + chunk) * 64 + t] = s;
    }
}

// ---------------- Kernel 3: reduce chunks + normalize context ---------------
__global__ __launch_bounds__(256) void ctx_reduce_kernel()
{
    const int bh = blockIdx.x;
    const int q  = blockIdx.y;
    const int t  = threadIdx.x;
    __shared__ float sinvS[64];
    if (t < 64) {
        const float* sp = g_spart + (size_t)bh * 256 + t;
        float s = sp[0] + sp[64] + sp[128] + sp[192];
        sinvS[t] = 1.0f / s;
    }
    __syncthreads();
    const float* cp = g_cpart + (size_t)bh * 16384;
    for (int idx = q * 1024 + t; idx < q * 1024 + 1024; idx += 256) {
        float c = cp[idx] + cp[idx + 4096] + cp[idx + 8192] + cp[idx + 12288];
        g_ctx[(size_t)bh * 4096 + idx] = c * sinvS[idx >> 6];
    }
}

// ---------------- Kernel 4: q-softmax (over d) + out = q_soft @ ctx ---------
__global__ __launch_bounds__(256) void out_kernel_f(float* __restrict__ out)
{
    const int nb = blockIdx.x;
    const int bh = blockIdx.y;
    const int b = bh >> 4, h = bh & 15;

    __shared__ __align__(16) float sctx[64][64];
    __shared__ __align__(16) float sq[64][68];
    __shared__ float prow[64][4];
    __shared__ float sinv[64];

    const int t = threadIdx.x;

    const float4* cg = (const float4*)(g_ctx + (size_t)bh * 4096);
    float4* cs = (float4*)sctx;
#pragma unroll
    for (int j = 0; j < 4; ++j) cs[t + 256 * j] = cg[t + 256 * j];

    const int r  = t >> 2;
    const int qp = t & 3;
    const float* qrow = g_qkv + ((size_t)(b * GN_SEQ + nb * 64 + r)) * GNO + h * 64;
    float psum = 0.0f;
#pragma unroll
    for (int c4 = 0; c4 < 4; ++c4) {
        int d0 = qp * 16 + c4 * 4;
        float4 qv = *(const float4*)(qrow + d0);
        float e0 = __expf(qv.x), e1 = __expf(qv.y), e2 = __expf(qv.z), e3 = __expf(qv.w);
        sq[r][d0] = e0; sq[r][d0 + 1] = e1; sq[r][d0 + 2] = e2; sq[r][d0 + 3] = e3;
        psum += e0 + e1 + e2 + e3;
    }
    prow[r][qp] = psum;
    __syncthreads();
    if (t < 64)
        sinv[t] = 0.125f / (prow[t][0] + prow[t][1] + prow[t][2] + prow[t][3]);
    __syncthreads();

    {
        float myinv = sinv[r];
#pragma unroll
        for (int c4 = 0; c4 < 4; ++c4) {
            int d0 = qp * 16 + c4 * 4;
            sq[r][d0] *= myinv; sq[r][d0 + 1] *= myinv;
            sq[r][d0 + 2] *= myinv; sq[r][d0 + 3] *= myinv;
        }
    }
    __syncthreads();

    const int rg  = t >> 4;
    const int egx = t & 15;
    float acc[4][4] = {{0}};
#pragma unroll 4
    for (int d = 0; d < 64; ++d) {
        float4 c4v = ((float4*)sctx[d])[egx];
#pragma unroll
        for (int i = 0; i < 4; ++i) {
            float qv = sq[rg * 4 + i][d];
            acc[i][0] += qv * c4v.x; acc[i][1] += qv * c4v.y;
            acc[i][2] += qv * c4v.z; acc[i][3] += qv * c4v.w;
        }
    }
#pragma unroll
    for (int i = 0; i < 4; ++i) {
        int n = nb * 64 + rg * 4 + i;
        ((float4*)(out + ((size_t)bh * GN_SEQ + n) * 64))[egx] =
            make_float4(acc[i][0], acc[i][1], acc[i][2], acc[i][3]);
    }
}

// ---------------- launcher ----------------------------------------------------
extern "C" void kernel_launch(void* const* d_in, const int* in_sizes, int n_in,
                              void* d_out, int out_size)
{
    const float* x = (const float*)d_in[0];     // [4,4096,1024]
    const float* w = (const float*)d_in[1];     // [3072,1024]
    float* out = (float*)d_out;                 // [4,16,4096,64]

    cudaFuncSetAttribute(qkv_gemm_f16,
                         cudaFuncAttributeMaxDynamicSharedMemorySize, GEMM_SMEM);

    split_kernel<<<4096, 256>>>(x, w);

    dim3 gGemm(GNO / BN, GM / BM);              // (24, 128) — N fastest for L2 reuse
    qkv_gemm_f16<<<gGemm, 256, GEMM_SMEM>>>();

    dim3 gCtx(64, 4);
    ctx_partial_kernel<<<gCtx, 512>>>();

    dim3 gRed(64, 4);
    ctx_reduce_kernel<<<gRed, 256>>>();

    dim3 gOut(64, 64);
    out_kernel_f<<<gOut, 256>>>(out);
}

// round 8
// speedup vs baseline: 2.1475x; 1.3392x over previous
#include <cuda_runtime.h>
#include <cuda_fp16.h>
#include <cstdint>

// Problem dims
#define GB     4
#define GN_SEQ 4096
#define GH     16
#define GD     64
#define GC     1024
#define GM     16384          // GB*GN_SEQ
#define GK     1024
#define GNO    3072           // 3*GC

// GEMM tiling: CTA 128x128, 8 warps of 64x32, BKK=64, 3 stages, occ 2
#define BM 128
#define BN 128
#define BKK 64
#define STAGES 3
#define STAGE_BYTES 32768               // A 16K | B 16K
#define GEMM_SMEM (STAGES * STAGE_BYTES)  // 96 KB -> 2 CTAs/SM

// ---------------- scratch (static device globals; no allocation) -------------
__device__ __half g_Ah[(size_t)GM * GK];       // 32 MB x fp16
__device__ __half g_Wh[(size_t)GNO * GK];      //  6 MB w fp16
__device__ __half g_qkv16[(size_t)GM * GNO];   // 96 MB qkv logits fp16
__device__ float  g_cpart[64 * 4 * 64 * 64];
__device__ float  g_spart[64 * 4 * 64];
__device__ __half g_ctx16[64 * 64 * 64];       // normalized context fp16 [bh][d][e]

// ---------------- asm helpers ------------------------------------------------
#define LDSM4(r, addr)                                                         \
    asm volatile("ldmatrix.sync.aligned.m8n8.x4.shared.b16 {%0,%1,%2,%3},[%4];"\
                 : "=r"((r)[0]), "=r"((r)[1]), "=r"((r)[2]), "=r"((r)[3])      \
                 : "r"(addr))

#define LDSM4T(r, addr)                                                        \
    asm volatile("ldmatrix.sync.aligned.m8n8.x4.trans.shared.b16 "             \
                 "{%0,%1,%2,%3},[%4];"                                         \
                 : "=r"((r)[0]), "=r"((r)[1]), "=r"((r)[2]), "=r"((r)[3])      \
                 : "r"(addr))

#define MMA_F16(d, a, b0, b1)                                                  \
    asm volatile("mma.sync.aligned.m16n8k16.row.col.f32.f16.f16.f32 "          \
                 "{%0,%1,%2,%3},{%4,%5,%6,%7},{%8,%9},{%0,%1,%2,%3};"          \
                 : "+f"((d)[0]), "+f"((d)[1]), "+f"((d)[2]), "+f"((d)[3])      \
                 : "r"((a)[0]), "r"((a)[1]), "r"((a)[2]), "r"((a)[3]),         \
                   "r"(b0), "r"(b1))

#define CP_ASYNC16(dst, src)                                                   \
    asm volatile("cp.async.cg.shared.global [%0],[%1],16;" ::                  \
                 "r"(dst), "l"(src) : "memory")
#define CP_COMMIT() asm volatile("cp.async.commit_group;" ::: "memory")
#define CP_WAIT1()  asm volatile("cp.async.wait_group 1;" ::: "memory")
#define CP_WAIT0()  asm volatile("cp.async.wait_group 0;" ::: "memory")

// ---------------- Kernel 0: fp32 -> fp16 convert pre-pass --------------------
__global__ __launch_bounds__(256) void split_kernel(const float* __restrict__ x,
                                                    const float* __restrict__ w)
{
    const size_t A4 = (size_t)GM * GK / 4;
    const size_t W4 = (size_t)GNO * GK / 4;
    const size_t total = A4 + W4;
    size_t stride = (size_t)gridDim.x * blockDim.x;
    for (size_t i = (size_t)blockIdx.x * blockDim.x + threadIdx.x; i < total; i += stride) {
        if (i < A4) {
            float4 v = ((const float4*)x)[i];
            ((__half2*)g_Ah)[i * 2]     = __floats2half2_rn(v.x, v.y);
            ((__half2*)g_Ah)[i * 2 + 1] = __floats2half2_rn(v.z, v.w);
        } else {
            size_t j = i - A4;
            float4 v = ((const float4*)w)[j];
            ((__half2*)g_Wh)[j * 2]     = __floats2half2_rn(v.x, v.y);
            ((__half2*)g_Wh)[j * 2 + 1] = __floats2half2_rn(v.z, v.w);
        }
    }
}

// ---------------- GEMM stage loader -------------------------------------------
__device__ __forceinline__ void issue_stage(int kt, int bm, int bn,
                                            unsigned sbase, int t)
{
    const int k0 = kt * BKK;
    const unsigned buf = sbase + (kt % STAGES) * STAGE_BYTES;
#pragma unroll
    for (int j = 0; j < 4; ++j) {
        int idx = t + j * 256;          // 0..1023
        int row = idx >> 3;
        int c   = idx & 7;
        unsigned soff = (unsigned)(row * 128 + ((c ^ (row & 7)) << 4));
        const __half* ga = g_Ah + (size_t)(bm + row) * GK + k0 + c * 8;
        CP_ASYNC16(buf + soff, ga);
        const __half* gb = g_Wh + (size_t)(bn + row) * GK + k0 + c * 8;
        CP_ASYNC16(buf + 16384 + soff, gb);
    }
}

// ---------------- Kernel 1: QKV GEMM (single fp16 MMA, occ 2) ---------------
__global__ __launch_bounds__(256, 2) void qkv_gemm_f16()
{
    extern __shared__ char smraw[];
    const unsigned sbase = (unsigned)__cvta_generic_to_shared(smraw);

    const int t    = threadIdx.x;
    const int bn   = blockIdx.x * BN;
    const int bm   = blockIdx.y * BM;
    const int lane = t & 31;
    const int warp = t >> 5;
    const int wm   = warp >> 2;
    const int wn   = warp & 3;

    const int lr = lane & 15;
    const int ls = lane >> 4;
    unsigned off[4];
#pragma unroll
    for (int g = 0; g < 4; ++g)
        off[g] = (unsigned)(lr * 128 + (((2 * g) + ls) ^ (lr & 7)) * 16);

    float acc[4][4][4];
#pragma unroll
    for (int i = 0; i < 4; ++i)
#pragma unroll
        for (int j = 0; j < 4; ++j)
#pragma unroll
            for (int c = 0; c < 4; ++c) acc[i][j][c] = 0.0f;

    issue_stage(0, bm, bn, sbase, t); CP_COMMIT();
    issue_stage(1, bm, bn, sbase, t); CP_COMMIT();

    const int NT = GK / BKK;   // 16
    for (int kt = 0; kt < NT; ++kt) {
        CP_WAIT1();
        __syncthreads();
        if (kt + 2 < NT)
            issue_stage(kt + 2, bm, bn, sbase, t);
        CP_COMMIT();

        const unsigned slot = sbase + (kt % STAGES) * STAGE_BYTES;
        const unsigned aBs  = slot +         (wm * 64) * 128;
        const unsigned bBs  = slot + 16384 + (wn * 32) * 128;

#pragma unroll
        for (int ks = 0; ks < 4; ++ks) {
            unsigned ah[4][4], bb[2][4];
#pragma unroll
            for (int mt = 0; mt < 4; ++mt)
                LDSM4(ah[mt], aBs + mt * 2048 + off[ks]);
#pragma unroll
            for (int p = 0; p < 2; ++p)
                LDSM4(bb[p], bBs + p * 2048 + off[ks]);
#pragma unroll
            for (int mt = 0; mt < 4; ++mt)
#pragma unroll
                for (int p = 0; p < 2; ++p)
#pragma unroll
                    for (int j = 0; j < 2; ++j)
                        MMA_F16(acc[mt][p * 2 + j], ah[mt], bb[p][j], bb[p][j + 2]);
        }
    }

    // epilogue -> fp16 logits
    const int g  = lane >> 2;
    const int tc = lane & 3;
#pragma unroll
    for (int mt = 0; mt < 4; ++mt)
#pragma unroll
        for (int nt = 0; nt < 4; ++nt) {
            int row = bm + wm * 64 + mt * 16 + g;
            int col = bn + wn * 32 + nt * 8 + tc * 2;
            *(__half2*)(g_qkv16 + (size_t)row * GNO + col) =
                __floats2half2_rn(acc[mt][nt][0], acc[mt][nt][1]);
            *(__half2*)(g_qkv16 + (size_t)(row + 8) * GNO + col) =
                __floats2half2_rn(acc[mt][nt][2], acc[mt][nt][3]);
        }
}

// ---------------- Kernel 2: ctx partial via mma ------------------------------
// Per (bh, chunk of 1024 tokens): C[d][e] = sum_n exp(k[n][d]) * v[n][e] (fp32
// acc), S[d] = sum_n exp(k[n][d]).  ek/v tiles in swizzled smem; both mma
// operands loaded with ldmatrix.trans (data is [n][*], operands need [*][n]).
__global__ __launch_bounds__(256) void ctx_partial_mma()
{
    const int bh    = blockIdx.x;
    const int chunk = blockIdx.y;
    const int b = bh >> 4, h = bh & 15;

    __shared__ __align__(16) __half sek[64 * 64];   // [n][d] swizzled, 8 KB
    __shared__ __align__(16) __half sv[64 * 64];    // [n][e] swizzled, 8 KB
    __shared__ float ps[32][64];

    const unsigned ekS = (unsigned)__cvta_generic_to_shared(sek);
    const unsigned vS  = (unsigned)__cvta_generic_to_shared(sv);

    const int t    = threadIdx.x;
    const int lane = t & 31;
    const int warp = t >> 5;
    const int wd   = warp >> 2;     // 0..1: d-half (32 rows)
    const int we   = warp & 3;      // 0..3: e-quarter (16 cols)

    // ldmatrix.trans lane->address components
    // A (ek -> A[d][n]): rowA selects n, chunk selects d16 within warp tile
    const int rowA_l = (lane & 7) + ((lane >> 4) << 3);
    const int chA_l  = (lane >> 3) & 1;
    // B (v -> B[n][e] col-major): rowB selects n, chunk selects e-chunk
    const int rowB_l = (lane & 7) + (((lane >> 3) & 1) << 3);
    const int chB_l  = lane >> 4;

    float acc[2][2][4];
#pragma unroll
    for (int i = 0; i < 2; ++i)
#pragma unroll
        for (int j = 0; j < 2; ++j)
#pragma unroll
            for (int c = 0; c < 4; ++c) acc[i][j][c] = 0.0f;
    float sacc[8] = {0, 0, 0, 0, 0, 0, 0, 0};

    const __half* kbase = g_qkv16 + ((size_t)b * GN_SEQ) * GNO + 1024 + h * 64;
    const __half* vbase = kbase + 1024;

    const int myrow = t >> 3;       // 0..31
    const int myc   = t & 7;        // fixed d-octet
    const unsigned soff0 = (unsigned)(myrow * 128 + ((myc ^ (myrow & 7)) << 4));
    const unsigned soff1 = (unsigned)((myrow + 32) * 128 +
                                      ((myc ^ ((myrow + 32) & 7)) << 4));

    for (int tile = 0; tile < 16; ++tile) {
        const int n0 = chunk * 1024 + tile * 64;
        // v tile via cp.async (swizzled)
        CP_ASYNC16(vS + soff0, vbase + (size_t)(n0 + myrow) * GNO + myc * 8);
        CP_ASYNC16(vS + soff1, vbase + (size_t)(n0 + myrow + 32) * GNO + myc * 8);
        CP_COMMIT();
        // k tile: load, exp (fp32), accumulate S partials, store fp16 swizzled
#pragma unroll
        for (int j = 0; j < 2; ++j) {
            const int row = myrow + j * 32;
            uint4 raw = *(const uint4*)(kbase + (size_t)(n0 + row) * GNO + myc * 8);
            const __half2* hp = (const __half2*)&raw;
            float e[8];
#pragma unroll
            for (int q = 0; q < 4; ++q) {
                float2 f = __half22float2(hp[q]);
                e[q * 2]     = __expf(f.x);
                e[q * 2 + 1] = __expf(f.y);
            }
#pragma unroll
            for (int q = 0; q < 8; ++q) sacc[q] += e[q];
            uint4 outv;
            __half2* op = (__half2*)&outv;
#pragma unroll
            for (int q = 0; q < 4; ++q)
                op[q] = __floats2half2_rn(e[q * 2], e[q * 2 + 1]);
            *(uint4*)((char*)sek + (j ? soff1 : soff0)) = outv;
        }
        CP_WAIT0();
        __syncthreads();

        // mma over this 64-token tile
#pragma unroll
        for (int ks = 0; ks < 4; ++ks) {
            const int rA = ks * 16 + rowA_l;
            const int rB = ks * 16 + rowB_l;
            unsigned af[2][4], bf[4];
#pragma unroll
            for (int mt = 0; mt < 2; ++mt) {
                int ch = (wd * 4 + mt * 2 + chA_l) ^ (rA & 7);
                LDSM4T(af[mt], ekS + (unsigned)(rA * 128 + ch * 16));
            }
            {
                int ch = (we * 2 + chB_l) ^ (rB & 7);
                LDSM4T(bf, vS + (unsigned)(rB * 128 + ch * 16));
            }
#pragma unroll
            for (int mt = 0; mt < 2; ++mt)
#pragma unroll
                for (int j = 0; j < 2; ++j)
                    MMA_F16(acc[mt][j], af[mt], bf[2 * j], bf[2 * j + 1]);
        }
        __syncthreads();
    }

    // write C partials
    const int g   = lane >> 2;
    const int tc2 = (lane & 3) * 2;
    const size_t cbase = ((size_t)(bh * 4 + chunk)) * 4096;
#pragma unroll
    for (int mt = 0; mt < 2; ++mt)
#pragma unroll
        for (int j = 0; j < 2; ++j) {
            int d = wd * 32 + mt * 16 + g;
            int e = we * 16 + j * 8 + tc2;
            *(float2*)(g_cpart + cbase + d * 64 + e) =
                make_float2(acc[mt][j][0], acc[mt][j][1]);
            *(float2*)(g_cpart + cbase + (d + 8) * 64 + e) =
                make_float2(acc[mt][j][2], acc[mt][j][3]);
        }

    // S reduce (fixed order)
#pragma unroll
    for (int q = 0; q < 8; ++q) ps[myrow][myc * 8 + q] = sacc[q];
    __syncthreads();
    if (t < 64) {
        float s = 0.0f;
#pragma unroll
        for (int i = 0; i < 32; ++i) s += ps[i][t];
        g_spart[(bh * 4 + chunk) * 64 + t] = s;
    }
}

// ---------------- Kernel 3: reduce chunks + normalize -> fp16 ctx -----------
__global__ __launch_bounds__(256) void ctx_reduce_kernel()
{
    const int bh = blockIdx.x;
    const int q  = blockIdx.y;
    const int t  = threadIdx.x;
    __shared__ float sinvS[64];
    if (t < 64) {
        const float* sp = g_spart + (size_t)bh * 256 + t;
        float s = sp[0] + sp[64] + sp[128] + sp[192];
        sinvS[t] = 1.0f / s;
    }
    __syncthreads();
    const float* cp = g_cpart + (size_t)bh * 16384;
    for (int idx = q * 1024 + t; idx < q * 1024 + 1024; idx += 256) {
        float c = cp[idx] + cp[idx + 4096] + cp[idx + 8192] + cp[idx + 12288];
        g_ctx16[(size_t)bh * 4096 + idx] = __float2half_rn(c * sinvS[idx >> 6]);
    }
}

// ---------------- Kernel 4: q-softmax + out via mma --------------------------
// Per (nb, bh): 64 tokens. A = q_soft fp16 [tok][d] (normal ldmatrix),
// B = ctx fp16 [d][e] (ldmatrix.trans -> col-major), fp32 acc -> out.
__global__ __launch_bounds__(256) void out_mma(float* __restrict__ out)
{
    const int nb = blockIdx.x;
    const int bh = blockIdx.y;
    const int b = bh >> 4, h = bh & 15;

    __shared__ __align__(16) __half sq[64 * 64];    // [tok][d] swizzled
    __shared__ __align__(16) __half sctx[64 * 64];  // [d][e] swizzled
    __shared__ float prow[64][8];
    __shared__ float sinv[64];

    const unsigned sqS = (unsigned)__cvta_generic_to_shared(sq);
    const unsigned scS = (unsigned)__cvta_generic_to_shared(sctx);

    const int t    = threadIdx.x;
    const int lane = t & 31;
    const int warp = t >> 5;
    const int wt   = warp >> 1;   // 0..3: 16-token group
    const int we   = warp & 1;    // 0..1: 32-col e half

    // ctx tile via cp.async (swizzled)
    {
        const int row = t >> 3, c = t & 7;
        unsigned s0 = (unsigned)(row * 128 + ((c ^ (row & 7)) << 4));
        unsigned s1 = (unsigned)((row + 32) * 128 + ((c ^ ((row + 32) & 7)) << 4));
        CP_ASYNC16(scS + s0, g_ctx16 + (size_t)bh * 4096 + row * 64 + c * 8);
        CP_ASYNC16(scS + s1, g_ctx16 + (size_t)bh * 4096 + (row + 32) * 64 + c * 8);
        CP_COMMIT();
    }

    // q: load fp16 logits, exp fp32 (kept in regs), partial row sums
    const int myrow = t >> 3;     // 0..31
    const int myc   = t & 7;
    const __half* qbase = g_qkv16 +
        ((size_t)(b * GN_SEQ + nb * 64)) * GNO + h * 64;
    float eq[2][8];
#pragma unroll
    for (int j = 0; j < 2; ++j) {
        const int row = myrow + j * 32;
        uint4 raw = *(const uint4*)(qbase + (size_t)row * GNO + myc * 8);
        const __half2* hp = (const __half2*)&raw;
        float psum = 0.0f;
#pragma unroll
        for (int q = 0; q < 4; ++q) {
            float2 f = __half22float2(hp[q]);
            eq[j][q * 2]     = __expf(f.x);
            eq[j][q * 2 + 1] = __expf(f.y);
            psum += eq[j][q * 2] + eq[j][q * 2 + 1];
        }
        prow[row][myc] = psum;
    }
    __syncthreads();
    if (t < 64) {
        const float* pr = prow[t];
        float s = pr[0] + pr[1] + pr[2] + pr[3] + pr[4] + pr[5] + pr[6] + pr[7];
        sinv[t] = 0.125f / s;
    }
    __syncthreads();
    // scale + store fp16 swizzled
#pragma unroll
    for (int j = 0; j < 2; ++j) {
        const int row = myrow + j * 32;
        const float inv = sinv[row];
        uint4 outv;
        __half2* op = (__half2*)&outv;
#pragma unroll
        for (int q = 0; q < 4; ++q)
            op[q] = __floats2half2_rn(eq[j][q * 2] * inv, eq[j][q * 2 + 1] * inv);
        unsigned soff = (unsigned)(row * 128 + ((myc ^ (row & 7)) << 4));
        *(uint4*)((char*)sq + soff) = outv;
    }
    CP_WAIT0();
    __syncthreads();

    // mma: warp tile 16 tok x 32 e, k = d (64)
    const int lr = lane & 15;
    const int ls = lane >> 4;
    const int rowB_l = (lane & 7) + (((lane >> 3) & 1) << 3);
    const int chB_l  = lane >> 4;

    float acc[4][4];
#pragma unroll
    for (int i = 0; i < 4; ++i)
#pragma unroll
        for (int c = 0; c < 4; ++c) acc[i][c] = 0.0f;

#pragma unroll
    for (int ks = 0; ks < 4; ++ks) {
        unsigned aq[4], bc[2][4];
        {
            unsigned offA = (unsigned)(lr * 128 + (((2 * ks) + ls) ^ (lr & 7)) * 16);
            LDSM4(aq, sqS + (unsigned)(wt * 16 * 128) + offA);
        }
        const int rB = ks * 16 + rowB_l;
#pragma unroll
        for (int p = 0; p < 2; ++p) {
            int ch = (we * 4 + p * 2 + chB_l) ^ (rB & 7);
            LDSM4T(bc[p], scS + (unsigned)(rB * 128 + ch * 16));
        }
#pragma unroll
        for (int p = 0; p < 2; ++p)
#pragma unroll
            for (int j = 0; j < 2; ++j)
                MMA_F16(acc[p * 2 + j], aq, bc[p][2 * j], bc[p][2 * j + 1]);
    }

    // epilogue
    const int g   = lane >> 2;
    const int tc2 = (lane & 3) * 2;
#pragma unroll
    for (int eb = 0; eb < 4; ++eb) {
        int tok = nb * 64 + wt * 16 + g;
        int e   = we * 32 + eb * 8 + tc2;
        *(float2*)(out + ((size_t)bh * GN_SEQ + tok) * 64 + e) =
            make_float2(acc[eb][0], acc[eb][1]);
        *(float2*)(out + ((size_t)bh * GN_SEQ + tok + 8) * 64 + e) =
            make_float2(acc[eb][2], acc[eb][3]);
    }
}

// ---------------- launcher ----------------------------------------------------
extern "C" void kernel_launch(void* const* d_in, const int* in_sizes, int n_in,
                              void* d_out, int out_size)
{
    const float* x = (const float*)d_in[0];     // [4,4096,1024]
    const float* w = (const float*)d_in[1];     // [3072,1024]
    float* out = (float*)d_out;                 // [4,16,4096,64]

    cudaFuncSetAttribute(qkv_gemm_f16,
                         cudaFuncAttributeMaxDynamicSharedMemorySize, GEMM_SMEM);

    split_kernel<<<4096, 256>>>(x, w);

    dim3 gGemm(GNO / BN, GM / BM);              // (24, 128)
    qkv_gemm_f16<<<gGemm, 256, GEMM_SMEM>>>();

    dim3 gCtx(64, 4);
    ctx_partial_mma<<<gCtx, 256>>>();

    dim3 gRed(64, 4);
    ctx_reduce_kernel<<<gRed, 256>>>();

    dim3 gOut(64, 64);
    out_mma<<<gOut, 256>>>(out);
}